// round 8
// baseline (speedup 1.0000x reference)
#include <cuda_runtime.h>
#include <cuda_bf16.h>

#define N_PART 1000000
#define N_GRID 128
#define N_NODES (N_GRID * N_GRID)
#define BLK 192
#define RUN 8
#define SLOTS_PER_BLK (BLK * RUN)   // 1536 slots, 48KB payload

// ---- device scratch (no runtime allocation allowed) ----
__device__ __align__(16) float4 g_node[N_NODES];   // (momx,momy,mass,pad)
__device__ float2 g_gv[N_NODES];
__device__ int g_cnt[N_NODES];
__device__ int g_off[N_NODES + 1];                 // exclusive scan + sentinel
__device__ int g_br[N_PART];                       // bin<<16 | rank
__device__ __align__(16) float4 g_pay[2 * N_PART]; // [2s]=(fx,fy,momx',momy') [2s+1]=(a00',a01',a10',a11')

__global__ void k_zero() {
    int n = blockIdx.x * blockDim.x + threadIdx.x;
    if (n < N_NODES) {
        g_node[n] = make_float4(0.f, 0.f, 0.f, 0.f);
        g_cnt[n] = 0;
    }
}

__global__ void __launch_bounds__(256) k_count(const float2* __restrict__ x) {
    int p = blockIdx.x * blockDim.x + threadIdx.x;
    if (p >= N_PART) return;
    float2 xp = x[p];
    int bx = (int)floorf(xp.x * 128.0f - 0.5f);
    int by = (int)floorf(xp.y * 128.0f - 0.5f);
    int bin = bx * N_GRID + by;
    int rank = atomicAdd(&g_cnt[bin], 1);
    g_br[p] = (bin << 16) | rank;
}

__global__ void __launch_bounds__(1024) k_scan() {
    __shared__ int s[1024];
    int tid = threadIdx.x;
    int base = tid * 16;
    int loc[16];
    int sum = 0;
    #pragma unroll
    for (int k = 0; k < 16; k++) { loc[k] = g_cnt[base + k]; sum += loc[k]; }
    s[tid] = sum;
    __syncthreads();
    for (int off = 1; off < 1024; off <<= 1) {
        int v = 0;
        if (tid >= off) v = s[tid - off];
        __syncthreads();
        if (tid >= off) s[tid] += v;
        __syncthreads();
    }
    int excl = s[tid] - sum;
    #pragma unroll
    for (int k = 0; k < 16; k++) {
        g_off[base + k] = excl;
        excl += loc[k];
    }
    if (tid == 1023) g_off[N_NODES] = excl;  // == N_PART
}

__global__ void __launch_bounds__(256) k_phys(
    const float2* __restrict__ x, const float2* __restrict__ v,
    const float4* __restrict__ C, const float4* __restrict__ F,
    const int* __restrict__ material, const float* __restrict__ Jp,
    float* __restrict__ out)
{
    int p = blockIdx.x * blockDim.x + threadIdx.x;
    if (p >= N_PART) return;

    const float DT = 1e-4f;
    const float INV_DX = 128.0f;
    const float DX = 1.0f / 128.0f;
    const float P_MASS = 1.52587890625e-05f;
    const float MU_0 = 1000.0f / (2.0f * 1.2f);
    const float LAM_0 = 1000.0f * 0.2f / (1.2f * 0.6f);

    float2 xp = x[p];
    float2 vp = v[p];
    float4 c = C[p];
    float4 f = F[p];
    int m = material[p];
    float jp = Jp[p];

    // F = F + DT * (C @ F)
    float f00 = f.x + DT * (c.x * f.x + c.y * f.z);
    float f01 = f.y + DT * (c.x * f.y + c.y * f.w);
    float f10 = f.z + DT * (c.z * f.x + c.w * f.z);
    float f11 = f.w + DT * (c.z * f.y + c.w * f.w);

    float h = (m == 1) ? 0.3f : expf(10.0f * (1.0f - jp));
    float mu = (m == 0) ? 0.0f : MU_0 * h;
    float lam = LAM_0 * h;

    // Singular values (algebraic)
    float E  = 0.5f * (f00 + f11);
    float Fm = 0.5f * (f00 - f11);
    float G  = 0.5f * (f10 + f01);
    float H  = 0.5f * (f10 - f01);
    float q2 = E * E + H * H;
    float invQ = rsqrtf(fmaxf(q2, 1e-30f));
    float Q  = q2 * invQ;
    float Rr = sqrtf(Fm * Fm + G * G);
    float sx = Q + Rr;
    float sy = Q - Rr;

    // Polar rotation R = U Vh (trig-free)
    float rc = E * invQ;
    float rs = H * invQ;
    float r00 = rc, r01 = -rs, r10 = rs, r11 = rc;

    float clx = fminf(fmaxf(sx, 0.975f), 1.0045f);
    float cly = fminf(fmaxf(sy, 0.975f), 1.0045f);
    float J;
    if (m == 2) {
        jp *= (sx * sy) / (clx * cly);
        J = clx * cly;
        // F_snow = F @ (V diag(clx/sx, cly/sy) V^T)
        float k00 = f00 * f00 + f10 * f10;
        float k11 = f01 * f01 + f11 * f11;
        float k01 = f00 * f01 + f10 * f11;
        float d  = 0.5f * (k00 - k11);
        float rr2 = d * d + k01 * k01;
        float invr = (rr2 > 1e-24f) ? rsqrtf(rr2) : 0.0f;
        float c2 = d * invr;
        float s2 = k01 * invr;
        float rr0 = clx / sx;
        float rr1 = cly / sy;
        float avg = 0.5f * (rr0 + rr1);
        float dif = 0.5f * (rr0 - rr1);
        float m00 = avg + c2 * dif;
        float m11 = avg - c2 * dif;
        float m01 = s2 * dif;
        float nf00 = f00 * m00 + f01 * m01;
        float nf01 = f00 * m01 + f01 * m11;
        float nf10 = f10 * m00 + f11 * m01;
        float nf11 = f10 * m01 + f11 * m11;
        f00 = nf00; f01 = nf01; f10 = nf10; f11 = nf11;
    } else {
        J = sx * sy;
        if (m == 0) {
            float sj = sqrtf(J);
            f00 = sj; f01 = 0.f; f10 = 0.f; f11 = sj;
        }
    }

    // stress = -DT * (2*mu*(F-R)@F^T + I*lam*J*(J-1))
    float d00 = f00 - r00, d01 = f01 - r01;
    float d10 = f10 - r10, d11 = f11 - r11;
    float tm = 2.0f * mu;
    float diag = lam * J * (J - 1.0f);
    float s00 = tm * (d00 * f00 + d01 * f01) + diag;
    float s01 = tm * (d00 * f10 + d01 * f11);
    float s10 = tm * (d10 * f00 + d11 * f01);
    float s11 = tm * (d10 * f10 + d11 * f11) + diag;
    const float scale = -1e-4f;  // -DT
    float a00 = scale * s00 + P_MASS * c.x;
    float a01 = scale * s01 + P_MASS * c.y;
    float a10 = scale * s10 + P_MASS * c.z;
    float a11 = scale * s11 + P_MASS * c.w;

    float momx = P_MASS * vp.x - (a00 * xp.x + a01 * xp.y);
    float momy = P_MASS * vp.y - (a10 * xp.x + a11 * xp.y);

    float bxf = floorf(xp.x * INV_DX - 0.5f);
    float byf = floorf(xp.y * INV_DX - 0.5f);
    float fxx = xp.x * INV_DX - bxf;
    float fxy = xp.y * INV_DX - byf;

    // Pre-fold node positions: contrib_x = wt*(momx' + i*a00' + j*a01')
    float momxp = momx + (a00 * bxf + a01 * byf) * DX;
    float momyp = momy + (a10 * bxf + a11 * byf) * DX;
    float a00p = a00 * DX, a01p = a01 * DX;
    float a10p = a10 * DX, a11p = a11 * DX;

    int br = g_br[p];
    int slot = g_off[br >> 16] + (br & 0xFFFF);
    g_pay[2 * slot]     = make_float4(fxx, fxy, momxp, momyp);
    g_pay[2 * slot + 1] = make_float4(a00p, a01p, a10p, a11p);

    // Outputs: F at 8M, material at 12M, Jp at 13M
    ((float4*)(out + 8000000))[p] = make_float4(f00, f01, f10, f11);
    out[12000000 + p] = (float)m;
    out[13000000 + p] = jp;
}

__device__ __forceinline__ void flush_cell(int cell, const float ax[9],
                                           const float ay[9], const float am[9]) {
    int bx = cell >> 7, by = cell & 127;
    #pragma unroll
    for (int i = 0; i < 3; i++) {
        #pragma unroll
        for (int j = 0; j < 3; j++) {
            int k = i * 3 + j;
            atomicAdd(&g_node[(bx + i) * N_GRID + (by + j)],
                      make_float4(ax[k], ay[k], am[k], 0.f));
        }
    }
}

__global__ void __launch_bounds__(BLK) k_p2g_sorted() {
    __shared__ float4 spay[2 * SLOTS_PER_BLK];   // 48KB
    int base_slot = blockIdx.x * SLOTS_PER_BLK;
    int nslots = min(SLOTS_PER_BLK, N_PART - base_slot);
    int nf4 = 2 * nslots;
    const float4* __restrict__ gp = &g_pay[2 * base_slot];
    for (int k = threadIdx.x; k < nf4; k += BLK) spay[k] = gp[k];
    __syncthreads();

    int s0 = base_slot + threadIdx.x * RUN;
    if (s0 >= N_PART) return;
    int send = min(s0 + RUN, N_PART);

    const float P_MASS = 1.52587890625e-05f;

    // binary search: largest cell with off[cell] <= s0
    int lo = 0, hi = N_NODES;
    while (hi - lo > 1) {
        int mid = (lo + hi) >> 1;
        if (g_off[mid] <= s0) lo = mid; else hi = mid;
    }
    int cell = lo;
    int bnd = g_off[cell + 1];

    float ax[9] = {0,0,0,0,0,0,0,0,0};
    float ay[9] = {0,0,0,0,0,0,0,0,0};
    float am[9] = {0,0,0,0,0,0,0,0,0};
    bool dirty = false;

    for (int s = s0; s < send; s++) {
        while (s >= bnd) {
            if (dirty) {
                flush_cell(cell, ax, ay, am);
                #pragma unroll
                for (int k = 0; k < 9; k++) { ax[k] = 0.f; ay[k] = 0.f; am[k] = 0.f; }
                dirty = false;
            }
            cell++;
            bnd = g_off[cell + 1];
        }
        int ls = s - base_slot;
        float4 pa = spay[2 * ls];
        float4 pb = spay[2 * ls + 1];
        float fxx = pa.x, fxy = pa.y, momx = pa.z, momy = pa.w;
        float wx[3], wy[3];
        wx[0] = 0.5f * (1.5f - fxx) * (1.5f - fxx);
        wx[1] = 0.75f - (fxx - 1.0f) * (fxx - 1.0f);
        wx[2] = 0.5f * (fxx - 0.5f) * (fxx - 0.5f);
        wy[0] = 0.5f * (1.5f - fxy) * (1.5f - fxy);
        wy[1] = 0.75f - (fxy - 1.0f) * (fxy - 1.0f);
        wy[2] = 0.5f * (fxy - 0.5f) * (fxy - 0.5f);
        #pragma unroll
        for (int i = 0; i < 3; i++) {
            float px = momx + (float)i * pb.x;
            float py = momy + (float)i * pb.z;
            #pragma unroll
            for (int j = 0; j < 3; j++) {
                float wt = wx[i] * wy[j];
                int k = i * 3 + j;
                ax[k] += wt * (px + (float)j * pb.y);
                ay[k] += wt * (py + (float)j * pb.w);
                am[k] += wt * P_MASS;
            }
        }
        dirty = true;
    }
    if (dirty) flush_cell(cell, ax, ay, am);
}

__global__ void k_grid() {
    int n = blockIdx.x * blockDim.x + threadIdx.x;
    if (n >= N_NODES) return;
    int i = n >> 7;
    int j = n & 127;
    const float DT = 1e-4f;

    float4 nd = g_node[n];
    float vx = nd.x, vy = nd.y, mm = nd.z;
    if (mm > 0.0f) {
        vx /= mm;
        vy /= mm;
        vy += -DT * 50.0f;
    }
    if (i < 3)    vx = fmaxf(vx, 0.0f);
    if (i >= 126) vx = fminf(vx, 0.0f);
    if (j < 3)    vy = fmaxf(vy, 0.0f);
    if (j >= 126) vy = fminf(vy, 0.0f);
    g_gv[n] = make_float2(vx, vy);
}

__global__ void __launch_bounds__(256) k_g2p(
    const float2* __restrict__ x, float* __restrict__ out)
{
    int p = blockIdx.x * blockDim.x + threadIdx.x;
    if (p >= N_PART) return;

    const float DT = 1e-4f;
    const float INV_DX = 128.0f;
    const float DX = 1.0f / 128.0f;

    float2 xp = x[p];
    float bxf = floorf(xp.x * INV_DX - 0.5f);
    float byf = floorf(xp.y * INV_DX - 0.5f);
    int bx = (int)bxf, by = (int)byf;
    float fxx = xp.x * INV_DX - bxf;
    float fxy = xp.y * INV_DX - byf;
    float wx[3], wy[3];
    wx[0] = 0.5f * (1.5f - fxx) * (1.5f - fxx);
    wx[1] = 0.75f - (fxx - 1.0f) * (fxx - 1.0f);
    wx[2] = 0.5f * (fxx - 0.5f) * (fxx - 0.5f);
    wy[0] = 0.5f * (1.5f - fxy) * (1.5f - fxy);
    wy[1] = 0.75f - (fxy - 1.0f) * (fxy - 1.0f);
    wy[2] = 0.5f * (fxy - 0.5f) * (fxy - 0.5f);

    float nvx = 0.f, nvy = 0.f;
    float b00 = 0.f, b01 = 0.f, b10 = 0.f, b11 = 0.f;

    #pragma unroll
    for (int i = 0; i < 3; i++) {
        float nodex = (float)(bx + i) * DX;
        #pragma unroll
        for (int j = 0; j < 3; j++) {
            float wt = wx[i] * wy[j];
            int idx = (bx + i) * N_GRID + (by + j);
            float2 gv = g_gv[idx];
            float nodey = (float)(by + j) * DX;
            nvx += wt * gv.x;
            nvy += wt * gv.y;
            b00 += wt * gv.x * nodex;
            b01 += wt * gv.x * nodey;
            b10 += wt * gv.y * nodex;
            b11 += wt * gv.y * nodey;
        }
    }

    const float k4 = 65536.0f;  // 4 * INV_DX^2
    float C00 = (b00 - nvx * xp.x) * k4;
    float C01 = (b01 - nvx * xp.y) * k4;
    float C10 = (b10 - nvy * xp.x) * k4;
    float C11 = (b11 - nvy * xp.y) * k4;

    ((float2*)out)[p] = make_float2(xp.x + DT * nvx, xp.y + DT * nvy);
    ((float2*)(out + 2000000))[p] = make_float2(nvx, nvy);
    ((float4*)(out + 4000000))[p] = make_float4(C00, C01, C10, C11);
}

extern "C" void kernel_launch(void* const* d_in, const int* in_sizes, int n_in,
                              void* d_out, int out_size) {
    const float2* x  = (const float2*)d_in[0];
    const float2* v  = (const float2*)d_in[1];
    const float4* C  = (const float4*)d_in[2];
    const float4* F  = (const float4*)d_in[3];
    const int* mat   = (const int*)d_in[4];
    const float* Jp  = (const float*)d_in[5];
    float* out = (float*)d_out;

    k_zero<<<(N_NODES + 255) / 256, 256>>>();
    k_count<<<(N_PART + 255) / 256, 256>>>(x);
    k_scan<<<1, 1024>>>();
    k_phys<<<(N_PART + 255) / 256, 256>>>(x, v, C, F, mat, Jp, out);
    k_p2g_sorted<<<(N_PART + SLOTS_PER_BLK - 1) / SLOTS_PER_BLK, BLK>>>();
    k_grid<<<(N_NODES + 255) / 256, 256>>>();
    k_g2p<<<(N_PART + 255) / 256, 256>>>(x, out);
}

// round 9
// speedup vs baseline: 1.3351x; 1.3351x over previous
#include <cuda_runtime.h>
#include <cuda_bf16.h>

#define N_PART 1000000
#define N_GRID 128
#define N_NODES (N_GRID * N_GRID)
#define NREP 32

// Grid scratch (device globals — no allocation allowed)
__device__ __align__(16) float4 g_node[NREP][N_NODES];  // (momx, momy, mass, pad)
__device__ float2 g_gv[N_NODES];   // final grid velocity for G2P

__global__ void k_zero() {
    int n = blockIdx.x * blockDim.x + threadIdx.x;
    if (n < N_NODES * NREP) {
        ((float4*)g_node)[n] = make_float4(0.f, 0.f, 0.f, 0.f);
    }
}

__global__ void __launch_bounds__(256) k_p2g(
    const float2* __restrict__ x, const float2* __restrict__ v,
    const float4* __restrict__ C, const float4* __restrict__ F,
    const int* __restrict__ material, const float* __restrict__ Jp,
    float* __restrict__ out)
{
    int p = blockIdx.x * blockDim.x + threadIdx.x;
    if (p >= N_PART) return;
    float4* __restrict__ rep = g_node[blockIdx.x & (NREP - 1)];

    const float DT = 1e-4f;
    const float INV_DX = 128.0f;
    const float DX = 1.0f / 128.0f;
    const float P_MASS = 1.52587890625e-05f;
    const float MU_0 = 1000.0f / (2.0f * 1.2f);
    const float LAM_0 = 1000.0f * 0.2f / (1.2f * 0.6f);

    float2 xp = x[p];
    float2 vp = v[p];
    float4 c = C[p];
    float4 f = F[p];
    int m = material[p];
    float jp = Jp[p];

    // F = F + DT * (C @ F)
    float f00 = f.x + DT * (c.x * f.x + c.y * f.z);
    float f01 = f.y + DT * (c.x * f.y + c.y * f.w);
    float f10 = f.z + DT * (c.z * f.x + c.w * f.z);
    float f11 = f.w + DT * (c.z * f.y + c.w * f.w);

    float h = (m == 1) ? 0.3f : expf(10.0f * (1.0f - jp));
    float mu = (m == 0) ? 0.0f : MU_0 * h;
    float lam = LAM_0 * h;

    // Singular values (algebraic)
    float E  = 0.5f * (f00 + f11);
    float Fm = 0.5f * (f00 - f11);
    float G  = 0.5f * (f10 + f01);
    float H  = 0.5f * (f10 - f01);
    float q2 = E * E + H * H;
    float invQ = rsqrtf(fmaxf(q2, 1e-30f));
    float Q  = q2 * invQ;
    float Rr = sqrtf(Fm * Fm + G * G);
    float sx = Q + Rr;
    float sy = Q - Rr;

    // Polar rotation R = U Vh (trig-free)
    float rc = E * invQ;
    float rs = H * invQ;
    float r00 = rc, r01 = -rs, r10 = rs, r11 = rc;

    float clx = fminf(fmaxf(sx, 0.975f), 1.0045f);
    float cly = fminf(fmaxf(sy, 0.975f), 1.0045f);
    float J;
    if (m == 2) {
        jp *= (sx * sy) / (clx * cly);
        J = clx * cly;
        // F_snow = F @ (V diag(clx/sx, cly/sy) V^T)
        float k00 = f00 * f00 + f10 * f10;
        float k11 = f01 * f01 + f11 * f11;
        float k01 = f00 * f01 + f10 * f11;
        float d  = 0.5f * (k00 - k11);
        float rr2 = d * d + k01 * k01;
        float invr = (rr2 > 1e-24f) ? rsqrtf(rr2) : 0.0f;
        float c2 = d * invr;
        float s2 = k01 * invr;
        float rr0 = clx / sx;
        float rr1 = cly / sy;
        float avg = 0.5f * (rr0 + rr1);
        float dif = 0.5f * (rr0 - rr1);
        float m00 = avg + c2 * dif;
        float m11 = avg - c2 * dif;
        float m01 = s2 * dif;
        float nf00 = f00 * m00 + f01 * m01;
        float nf01 = f00 * m01 + f01 * m11;
        float nf10 = f10 * m00 + f11 * m01;
        float nf11 = f10 * m01 + f11 * m11;
        f00 = nf00; f01 = nf01; f10 = nf10; f11 = nf11;
    } else {
        J = sx * sy;
        if (m == 0) {
            float sj = sqrtf(J);
            f00 = sj; f01 = 0.f; f10 = 0.f; f11 = sj;
        }
    }

    // stress = -DT * (2*mu*(F-R)@F^T + I*lam*J*(J-1))
    float d00 = f00 - r00, d01 = f01 - r01;
    float d10 = f10 - r10, d11 = f11 - r11;
    float tm = 2.0f * mu;
    float diag = lam * J * (J - 1.0f);
    float s00 = tm * (d00 * f00 + d01 * f01) + diag;
    float s01 = tm * (d00 * f10 + d01 * f11);
    float s10 = tm * (d10 * f00 + d11 * f01);
    float s11 = tm * (d10 * f10 + d11 * f11) + diag;
    const float scale = -1e-4f;  // -DT
    float a00 = scale * s00 + P_MASS * c.x;
    float a01 = scale * s01 + P_MASS * c.y;
    float a10 = scale * s10 + P_MASS * c.z;
    float a11 = scale * s11 + P_MASS * c.w;

    float momx = P_MASS * vp.x - (a00 * xp.x + a01 * xp.y);
    float momy = P_MASS * vp.y - (a10 * xp.x + a11 * xp.y);

    float bxf = floorf(xp.x * INV_DX - 0.5f);
    float byf = floorf(xp.y * INV_DX - 0.5f);
    int bx = (int)bxf, by = (int)byf;
    float fxx = xp.x * INV_DX - bxf;
    float fxy = xp.y * INV_DX - byf;
    float wx[3], wy[3];
    wx[0] = 0.5f * (1.5f - fxx) * (1.5f - fxx);
    wx[1] = 0.75f - (fxx - 1.0f) * (fxx - 1.0f);
    wx[2] = 0.5f * (fxx - 0.5f) * (fxx - 0.5f);
    wy[0] = 0.5f * (1.5f - fxy) * (1.5f - fxy);
    wy[1] = 0.75f - (fxy - 1.0f) * (fxy - 1.0f);
    wy[2] = 0.5f * (fxy - 0.5f) * (fxy - 0.5f);

    // Fold affine into momentum: contrib = wt * (mom + A @ node_pos)
    #pragma unroll
    for (int i = 0; i < 3; i++) {
        float nodex = (float)(bx + i) * DX;
        float axx = a00 * nodex;
        float ayx = a10 * nodex;
        #pragma unroll
        for (int j = 0; j < 3; j++) {
            float nodey = (float)(by + j) * DX;
            float wt = wx[i] * wy[j];
            int idx = (bx + i) * N_GRID + (by + j);
            float cx = wt * (momx + axx + a01 * nodey);
            float cy = wt * (momy + ayx + a11 * nodey);
            atomicAdd(&rep[idx], make_float4(cx, cy, wt * P_MASS, 0.f));
        }
    }

    // Outputs (streaming stores — keep L2 for the atomic working set)
    __stcs((float4*)(out + 8000000) + p, make_float4(f00, f01, f10, f11));
    __stcs(out + 12000000 + p, (float)m);
    __stcs(out + 13000000 + p, jp);
}

__global__ void k_grid() {
    int n = blockIdx.x * blockDim.x + threadIdx.x;
    if (n >= N_NODES) return;
    int i = n >> 7;
    int j = n & 127;
    const float DT = 1e-4f;

    float vx = 0.f, vy = 0.f, mm = 0.f;
    #pragma unroll
    for (int r = 0; r < NREP; r++) {
        float4 nd = g_node[r][n];
        vx += nd.x; vy += nd.y; mm += nd.z;
    }
    if (mm > 0.0f) {
        vx /= mm;
        vy /= mm;
        vy += -DT * 50.0f;
    }
    if (i < 3)    vx = fmaxf(vx, 0.0f);
    if (i >= 126) vx = fminf(vx, 0.0f);
    if (j < 3)    vy = fmaxf(vy, 0.0f);
    if (j >= 126) vy = fminf(vy, 0.0f);
    g_gv[n] = make_float2(vx, vy);
}

__global__ void __launch_bounds__(256) k_g2p(
    const float2* __restrict__ x, float* __restrict__ out)
{
    int p = blockIdx.x * blockDim.x + threadIdx.x;
    if (p >= N_PART) return;

    const float DT = 1e-4f;
    const float INV_DX = 128.0f;
    const float DX = 1.0f / 128.0f;

    float2 xp = x[p];
    float bxf = floorf(xp.x * INV_DX - 0.5f);
    float byf = floorf(xp.y * INV_DX - 0.5f);
    int bx = (int)bxf, by = (int)byf;
    float fxx = xp.x * INV_DX - bxf;
    float fxy = xp.y * INV_DX - byf;
    float wx[3], wy[3];
    wx[0] = 0.5f * (1.5f - fxx) * (1.5f - fxx);
    wx[1] = 0.75f - (fxx - 1.0f) * (fxx - 1.0f);
    wx[2] = 0.5f * (fxx - 0.5f) * (fxx - 0.5f);
    wy[0] = 0.5f * (1.5f - fxy) * (1.5f - fxy);
    wy[1] = 0.75f - (fxy - 1.0f) * (fxy - 1.0f);
    wy[2] = 0.5f * (fxy - 0.5f) * (fxy - 0.5f);

    float nvx = 0.f, nvy = 0.f;
    float b00 = 0.f, b01 = 0.f, b10 = 0.f, b11 = 0.f;

    #pragma unroll
    for (int i = 0; i < 3; i++) {
        float nodex = (float)(bx + i) * DX;
        #pragma unroll
        for (int j = 0; j < 3; j++) {
            float wt = wx[i] * wy[j];
            int idx = (bx + i) * N_GRID + (by + j);
            float2 gv = g_gv[idx];
            float nodey = (float)(by + j) * DX;
            nvx += wt * gv.x;
            nvy += wt * gv.y;
            b00 += wt * gv.x * nodex;
            b01 += wt * gv.x * nodey;
            b10 += wt * gv.y * nodex;
            b11 += wt * gv.y * nodey;
        }
    }

    const float k4 = 65536.0f;  // 4 * INV_DX^2
    float C00 = (b00 - nvx * xp.x) * k4;
    float C01 = (b01 - nvx * xp.y) * k4;
    float C10 = (b10 - nvy * xp.x) * k4;
    float C11 = (b11 - nvy * xp.y) * k4;

    __stcs((float2*)out + p, make_float2(xp.x + DT * nvx, xp.y + DT * nvy));
    __stcs((float2*)(out + 2000000) + p, make_float2(nvx, nvy));
    __stcs((float4*)(out + 4000000) + p, make_float4(C00, C01, C10, C11));
}

extern "C" void kernel_launch(void* const* d_in, const int* in_sizes, int n_in,
                              void* d_out, int out_size) {
    const float2* x  = (const float2*)d_in[0];
    const float2* v  = (const float2*)d_in[1];
    const float4* C  = (const float4*)d_in[2];
    const float4* F  = (const float4*)d_in[3];
    const int* mat   = (const int*)d_in[4];
    const float* Jp  = (const float*)d_in[5];
    float* out = (float*)d_out;

    k_zero<<<(N_NODES * NREP + 255) / 256, 256>>>();
    k_p2g<<<(N_PART + 255) / 256, 256>>>(x, v, C, F, mat, Jp, out);
    k_grid<<<(N_NODES + 255) / 256, 256>>>();
    k_g2p<<<(N_PART + 255) / 256, 256>>>(x, out);
}